// round 12
// baseline (speedup 1.0000x reference)
#include <cuda_runtime.h>
#include <cuda_fp16.h>
#include <cstdint>

#define CIN 16
#define COUT 32
#define K2 9
#define MAXN 2000000
#define WSTR 40        // weight SMEM row stride in halves (80 B)
#define AROW 80        // A-tile row stride bytes (both convs)
#define BUFB (64 * AROW)   // one tap buffer per warp: 5120 B

// fp16 intermediate h1 (128 MB ~ L2-resident) and fp16 copy of x (64 MB).
__device__ __align__(256) __half g_h1h[(size_t)MAXN * COUT];
__device__ __align__(256) __half g_xh[(size_t)MAXN * CIN];
// fused gather index: cidx = mask ? idx : -1
__device__ int g_cidx[(size_t)K2 * MAXN];
// fp16 weights (compact)
__device__ __half g_w1h[K2 * CIN * COUT];
__device__ __half g_w2h[K2 * COUT * COUT];
__device__ __half g_wph[CIN * COUT];

// ---- PTX wrappers ----
__device__ __forceinline__ void ldg256(const void* p, uint4& a, uint4& b) {
    asm("ld.global.nc.v8.b32 {%0,%1,%2,%3,%4,%5,%6,%7}, [%8];"
        : "=r"(a.x), "=r"(a.y), "=r"(a.z), "=r"(a.w),
          "=r"(b.x), "=r"(b.y), "=r"(b.z), "=r"(b.w)
        : "l"(p));
}
__device__ __forceinline__ void cpa16(unsigned dst, const void* src, unsigned ssz) {
    asm volatile("cp.async.ca.shared.global [%0], [%1], 16, %2;"
                 :: "r"(dst), "l"(src), "r"(ssz));
}
__device__ __forceinline__ void cp_commit() {
    asm volatile("cp.async.commit_group;" ::: "memory");
}
template <int N>
__device__ __forceinline__ void cp_wait() {
    asm volatile("cp.async.wait_group %0;" :: "n"(N) : "memory");
}
__device__ __forceinline__ void ldsm4(unsigned r[4], unsigned addr) {
    asm volatile("ldmatrix.sync.aligned.m8n8.x4.shared.b16 {%0,%1,%2,%3}, [%4];"
                 : "=r"(r[0]), "=r"(r[1]), "=r"(r[2]), "=r"(r[3]) : "r"(addr));
}
__device__ __forceinline__ void ldsm4t(unsigned r[4], unsigned addr) {
    asm volatile("ldmatrix.sync.aligned.m8n8.x4.trans.shared.b16 {%0,%1,%2,%3}, [%4];"
                 : "=r"(r[0]), "=r"(r[1]), "=r"(r[2]), "=r"(r[3]) : "r"(addr));
}
__device__ __forceinline__ void mma16816(float c[4], const unsigned a[4],
                                         unsigned b0, unsigned b1) {
    asm("mma.sync.aligned.m16n8k16.row.col.f32.f16.f16.f32 "
        "{%0,%1,%2,%3}, {%4,%5,%6,%7}, {%8,%9}, {%0,%1,%2,%3};"
        : "+f"(c[0]), "+f"(c[1]), "+f"(c[2]), "+f"(c[3])
        : "r"(a[0]), "r"(a[1]), "r"(a[2]), "r"(a[3]), "r"(b0), "r"(b1));
}

// =====================================================================
// prologues
// =====================================================================
__global__ __launch_bounds__(256)
void fuse_kernel(const int* __restrict__ idx, const unsigned* __restrict__ mask, int total) {
    int i = blockIdx.x * blockDim.x + threadIdx.x;
    int stride = gridDim.x * blockDim.x;
    int t4 = total >> 2;
    const int4* i4 = (const int4*)idx;
    const uint4* m4 = (const uint4*)mask;
    int4* c4 = (int4*)g_cidx;
    for (int j = i; j < t4; j += stride) {
        int4 v = i4[j]; uint4 m = m4[j];
        v.x = m.x ? v.x : -1;  v.y = m.y ? v.y : -1;
        v.z = m.z ? v.z : -1;  v.w = m.w ? v.w : -1;
        c4[j] = v;
    }
    if (i == 0)
        for (int j = t4 * 4; j < total; j++) g_cidx[j] = mask[j] ? idx[j] : -1;
}

__global__ __launch_bounds__(256)
void xh_kernel(const float* __restrict__ x, int n) {
    int total8 = n * CIN / 8;
    int stride = gridDim.x * blockDim.x;
    const float4* x4 = (const float4*)x;
    uint4* o4 = (uint4*)g_xh;
    for (int j = blockIdx.x * blockDim.x + threadIdx.x; j < total8; j += stride) {
        float4 a = __ldg(x4 + 2 * j), b = __ldg(x4 + 2 * j + 1);
        uint4 o; __half2 h;
        h = __floats2half2_rn(a.x, a.y); o.x = *(unsigned*)&h;
        h = __floats2half2_rn(a.z, a.w); o.y = *(unsigned*)&h;
        h = __floats2half2_rn(b.x, b.y); o.z = *(unsigned*)&h;
        h = __floats2half2_rn(b.z, b.w); o.w = *(unsigned*)&h;
        o4[j] = o;
    }
}

__global__ __launch_bounds__(256)
void wcvt_kernel(const float* __restrict__ W1, const float* __restrict__ W2,
                 const float* __restrict__ Wp) {
    int i = blockIdx.x * 256 + threadIdx.x;
    if (i < K2 * CIN * COUT)  g_w1h[i] = __float2half(W1[i]);
    if (i < K2 * COUT * COUT) g_w2h[i] = __float2half(W2[i]);
    if (i < CIN * COUT)       g_wph[i] = __float2half(Wp[i]);
}

// =====================================================================
// conv1: h1(fp16) = relu( sum_k x_h[cidx] @ W1[k] + b1 )
// warp tile M=64; taps fused pairwise -> 5 super-taps of K=32 (tap 9 = 0).
// cp.async double-buffered A staging, depth 2, warp-local.
// =====================================================================
__global__ __launch_bounds__(256, 2)
void conv1_kernel(const float* __restrict__ b1, int n) {
    extern __shared__ char smem[];
    __half* atile = (__half*)smem;                         // 8 warps * 2 bufs * 5120 B
    __half* wsm   = (__half*)(smem + 8 * 2 * BUFB);        // 10 taps * 16 * WSTR halves
    float*  bsm   = (float*)(wsm + 10 * CIN * WSTR);

    const int t = threadIdx.x, lane = t & 31, w = t >> 5;
    for (int i = t; i < 10 * CIN * COUT; i += 256) {
        int row = i >> 5, cc = i & 31;
        wsm[row * WSTR + cc] = (i < K2 * CIN * COUT) ? g_w1h[i] : __float2half(0.f);
    }
    if (t < COUT) bsm[t] = __ldg(b1 + t);
    __syncthreads();

    const int grp = lane >> 2, tig = lane & 3;
    const int sub = lane & 7, ti = lane >> 3;
    const int v0w = blockIdx.x * 512 + w * 64;
    const int vA = v0w + lane, vB = vA + 32;

    const unsigned abuf0 =
        (unsigned)__cvta_generic_to_shared((char*)atile + w * 2 * BUFB);
    const unsigned wb0 = (unsigned)__cvta_generic_to_shared(wsm);
    const int lro = sub + ((ti & 1) << 3);
    const int lco = (ti >> 1) << 4;

    float acc[4][4][4];
#pragma unroll
    for (int m = 0; m < 4; m++)
#pragma unroll
        for (int nt = 0; nt < 4; nt++) {
            float c0 = bsm[8 * nt + 2 * tig], c1 = bsm[8 * nt + 2 * tig + 1];
            acc[m][nt][0] = c0; acc[m][nt][1] = c1;
            acc[m][nt][2] = c0; acc[m][nt][3] = c1;
        }

    // issue super-tap j (taps 2j, 2j+1) into buffer buf
    auto issue_pair = [&](int j, int buf) {
        int k0 = 2 * j, k1 = 2 * j + 1;
        int cA0 = (vA < n) ? __ldg(g_cidx + (size_t)k0 * n + vA) : -1;
        int cB0 = (vB < n) ? __ldg(g_cidx + (size_t)k0 * n + vB) : -1;
        int cA1 = (k1 < K2 && vA < n) ? __ldg(g_cidx + (size_t)k1 * n + vA) : -1;
        int cB1 = (k1 < K2 && vB < n) ? __ldg(g_cidx + (size_t)k1 * n + vB) : -1;
        const char* pA0 = (const char*)(g_xh + (size_t)(cA0 < 0 ? 0 : cA0) * CIN);
        const char* pB0 = (const char*)(g_xh + (size_t)(cB0 < 0 ? 0 : cB0) * CIN);
        const char* pA1 = (const char*)(g_xh + (size_t)(cA1 < 0 ? 0 : cA1) * CIN);
        const char* pB1 = (const char*)(g_xh + (size_t)(cB1 < 0 ? 0 : cB1) * CIN);
        unsigned sA0 = (cA0 >= 0) ? 16u : 0u, sB0 = (cB0 >= 0) ? 16u : 0u;
        unsigned sA1 = (cA1 >= 0) ? 16u : 0u, sB1 = (cB1 >= 0) ? 16u : 0u;
        unsigned dA = abuf0 + buf * BUFB + lane * AROW;
        unsigned dB = dA + 32 * AROW;
        cpa16(dA,      pA0,      sA0);
        cpa16(dA + 16, pA0 + 16, sA0);
        cpa16(dA + 32, pA1,      sA1);
        cpa16(dA + 48, pA1 + 16, sA1);
        cpa16(dB,      pB0,      sB0);
        cpa16(dB + 16, pB0 + 16, sB0);
        cpa16(dB + 32, pB1,      sB1);
        cpa16(dB + 48, pB1 + 16, sB1);
        cp_commit();
    };

    issue_pair(0, 0);
    issue_pair(1, 1);

#pragma unroll
    for (int j = 0; j < 5; j++) {
        if (j < 4) cp_wait<1>(); else cp_wait<0>();
        __syncwarp();
        const unsigned abuf = abuf0 + (j & 1) * BUFB;
        unsigned wtap = wb0 + j * (32 * WSTR * 2);
#pragma unroll
        for (int kt = 0; kt < 2; kt++) {
            unsigned bw[8];
            unsigned wk = wtap + (16 * kt + lro) * (WSTR * 2) + lco;
            ldsm4t(bw,     wk);
            ldsm4t(bw + 4, wk + 32);
#pragma unroll
            for (int m = 0; m < 4; m++) {
                unsigned av[4];
                ldsm4(av, abuf + (16 * m + lro) * AROW + kt * 32 + lco);
                mma16816(acc[m][0], av, bw[0], bw[1]);
                mma16816(acc[m][1], av, bw[2], bw[3]);
                mma16816(acc[m][2], av, bw[4], bw[5]);
                mma16816(acc[m][3], av, bw[6], bw[7]);
            }
        }
        __syncwarp();
        if (j + 2 < 5) issue_pair(j + 2, j & 1);
    }

    // epilogue: relu -> fp16 h1
#pragma unroll
    for (int m = 0; m < 4; m++) {
        int vg0 = v0w + 16 * m + grp, vg1 = vg0 + 8;
#pragma unroll
        for (int nt = 0; nt < 4; nt++) {
            const float* a = acc[m][nt];
            if (vg0 < n) {
                __half2 h = __floats2half2_rn(fmaxf(a[0], 0.f), fmaxf(a[1], 0.f));
                *(__half2*)(g_h1h + (size_t)vg0 * COUT + 8 * nt + 2 * tig) = h;
            }
            if (vg1 < n) {
                __half2 h = __floats2half2_rn(fmaxf(a[2], 0.f), fmaxf(a[3], 0.f));
                *(__half2*)(g_h1h + (size_t)vg1 * COUT + 8 * nt + 2 * tig) = h;
            }
        }
    }
}

// =====================================================================
// conv2 + residual: out = relu( sum_k h1[cidx] @ W2[k] + x_h @ Wp + b2 + bp )
// warp tile M=64, 9 taps K=32; cp.async depth-2; proj up front.
// =====================================================================
__global__ __launch_bounds__(256, 2)
void conv2_kernel(const float* __restrict__ b2, const float* __restrict__ bp,
                  float* __restrict__ out, int n) {
    extern __shared__ char smem[];
    __half* atile = (__half*)smem;                          // 8 * 2 * 5120 B
    __half* wsm   = (__half*)(smem + 8 * 2 * BUFB);         // 9*32*WSTR halves
    __half* wpsm  = wsm + K2 * COUT * WSTR;                 // 16*WSTR halves
    float*  bsm   = (float*)(wpsm + CIN * WSTR);

    const int t = threadIdx.x, lane = t & 31, w = t >> 5;
    for (int i = t; i < K2 * COUT * COUT; i += 256) {
        int row = i >> 5, cc = i & 31;
        wsm[row * WSTR + cc] = g_w2h[i];
    }
    for (int i = t; i < CIN * COUT; i += 256) {
        int row = i >> 5, cc = i & 31;
        wpsm[row * WSTR + cc] = g_wph[i];
    }
    if (t < COUT) bsm[t] = __ldg(b2 + t) + __ldg(bp + t);
    __syncthreads();

    const int grp = lane >> 2, tig = lane & 3;
    const int sub = lane & 7, ti = lane >> 3;
    const int v0w = blockIdx.x * 512 + w * 64;
    const int vA = v0w + lane, vB = vA + 32;

    const unsigned abuf0 =
        (unsigned)__cvta_generic_to_shared((char*)atile + w * 2 * BUFB);
    const unsigned wb0 = (unsigned)__cvta_generic_to_shared(wsm);
    const unsigned wpb = (unsigned)__cvta_generic_to_shared(wpsm);
    const int lro = sub + ((ti & 1) << 3);
    const int lco = (ti >> 1) << 4;

    float acc[4][4][4];
#pragma unroll
    for (int m = 0; m < 4; m++)
#pragma unroll
        for (int nt = 0; nt < 4; nt++) {
            float c0 = bsm[8 * nt + 2 * tig], c1 = bsm[8 * nt + 2 * tig + 1];
            acc[m][nt][0] = c0; acc[m][nt][1] = c1;
            acc[m][nt][2] = c0; acc[m][nt][3] = c1;
        }

    // ---- stage proj rows into buf0, snapshot frags, then start pipeline ----
    unsigned avp[4][4], bwp[8];
    {
        uint4 p0, p1;
        char* arowA = (char*)atile + w * 2 * BUFB + lane * AROW;
        if (vA < n) {
            ldg256(g_xh + (size_t)vA * CIN, p0, p1);
        } else { p0 = make_uint4(0,0,0,0); p1 = p0; }
        ((uint4*)arowA)[0] = p0; ((uint4*)arowA)[1] = p1;
        if (vB < n) {
            ldg256(g_xh + (size_t)vB * CIN, p0, p1);
        } else { p0 = make_uint4(0,0,0,0); p1 = p0; }
        char* arowB = arowA + 32 * AROW;
        ((uint4*)arowB)[0] = p0; ((uint4*)arowB)[1] = p1;
        __syncwarp();
        unsigned wp0 = wpb + lro * (WSTR * 2) + lco;
        ldsm4t(bwp,     wp0);
        ldsm4t(bwp + 4, wp0 + 32);
#pragma unroll
        for (int m = 0; m < 4; m++)
            ldsm4(avp[m], abuf0 + (16 * m + lro) * AROW + lco);
        __syncwarp();     // all lanes done reading buf0 before cp.async overwrites
    }

    auto issue_tap = [&](int k, int buf) {
        int ciA = (vA < n) ? __ldg(g_cidx + (size_t)k * n + vA) : -1;
        int ciB = (vB < n) ? __ldg(g_cidx + (size_t)k * n + vB) : -1;
        const char* pA = (const char*)(g_h1h + (size_t)(ciA < 0 ? 0 : ciA) * COUT);
        const char* pB = (const char*)(g_h1h + (size_t)(ciB < 0 ? 0 : ciB) * COUT);
        unsigned sA = (ciA >= 0) ? 16u : 0u, sB = (ciB >= 0) ? 16u : 0u;
        unsigned dA = abuf0 + buf * BUFB + lane * AROW;
        unsigned dB = dA + 32 * AROW;
        cpa16(dA,      pA,      sA);
        cpa16(dA + 16, pA + 16, sA);
        cpa16(dA + 32, pA + 32, sA);
        cpa16(dA + 48, pA + 48, sA);
        cpa16(dB,      pB,      sB);
        cpa16(dB + 16, pB + 16, sB);
        cpa16(dB + 32, pB + 32, sB);
        cpa16(dB + 48, pB + 48, sB);
        cp_commit();
    };

    issue_tap(0, 0);
    issue_tap(1, 1);

    // proj MMA from snapshotted frags (overlaps taps 0/1 loads)
#pragma unroll
    for (int m = 0; m < 4; m++) {
        mma16816(acc[m][0], avp[m], bwp[0], bwp[1]);
        mma16816(acc[m][1], avp[m], bwp[2], bwp[3]);
        mma16816(acc[m][2], avp[m], bwp[4], bwp[5]);
        mma16816(acc[m][3], avp[m], bwp[6], bwp[7]);
    }

#pragma unroll
    for (int k = 0; k < K2; k++) {
        if (k < K2 - 1) cp_wait<1>(); else cp_wait<0>();
        __syncwarp();
        const unsigned abuf = abuf0 + (k & 1) * BUFB;
        unsigned wtap = wb0 + k * (COUT * WSTR * 2);
#pragma unroll
        for (int kt = 0; kt < 2; kt++) {
            unsigned bw[8];
            unsigned wk = wtap + (16 * kt + lro) * (WSTR * 2) + lco;
            ldsm4t(bw,     wk);
            ldsm4t(bw + 4, wk + 32);
#pragma unroll
            for (int m = 0; m < 4; m++) {
                unsigned av[4];
                ldsm4(av, abuf + (16 * m + lro) * AROW + kt * 32 + lco);
                mma16816(acc[m][0], av, bw[0], bw[1]);
                mma16816(acc[m][1], av, bw[2], bw[3]);
                mma16816(acc[m][2], av, bw[4], bw[5]);
                mma16816(acc[m][3], av, bw[6], bw[7]);
            }
        }
        __syncwarp();
        if (k + 2 < K2) issue_tap(k + 2, k & 1);
    }

    // epilogue: relu -> fp32 out
#pragma unroll
    for (int m = 0; m < 4; m++) {
        int vg0 = v0w + 16 * m + grp, vg1 = vg0 + 8;
#pragma unroll
        for (int nt = 0; nt < 4; nt++) {
            const float* a = acc[m][nt];
            if (vg0 < n)
                *(float2*)(out + (size_t)vg0 * COUT + 8 * nt + 2 * tig) =
                    make_float2(fmaxf(a[0], 0.f), fmaxf(a[1], 0.f));
            if (vg1 < n)
                *(float2*)(out + (size_t)vg1 * COUT + 8 * nt + 2 * tig) =
                    make_float2(fmaxf(a[2], 0.f), fmaxf(a[3], 0.f));
        }
    }
}

// =====================================================================
// Launch.  Input order: x, W1, b1, W2, b2, Wp, bp, nbr_idx, nbr_mask
// =====================================================================
extern "C" void kernel_launch(void* const* d_in, const int* in_sizes, int n_in,
                              void* d_out, int out_size) {
    const float* x  = (const float*)d_in[0];
    const float* W1 = (const float*)d_in[1];
    const float* b1 = (const float*)d_in[2];
    const float* W2 = (const float*)d_in[3];
    const float* b2 = (const float*)d_in[4];
    const float* Wp = (const float*)d_in[5];
    const float* bp = (const float*)d_in[6];
    const int* nbr_idx = (const int*)d_in[7];
    const unsigned* nbr_mask = (const unsigned*)d_in[8];
    float* out = (float*)d_out;

    int n = in_sizes[0] / CIN;
    if (n > MAXN) n = MAXN;

    const int smem1 = 8 * 2 * BUFB + 10 * CIN * WSTR * 2 + COUT * 4;
    const int smem2 = 8 * 2 * BUFB + K2 * COUT * WSTR * 2 + CIN * WSTR * 2 + COUT * 4;
    cudaFuncSetAttribute(conv1_kernel, cudaFuncAttributeMaxDynamicSharedMemorySize, smem1);
    cudaFuncSetAttribute(conv2_kernel, cudaFuncAttributeMaxDynamicSharedMemorySize, smem2);

    fuse_kernel<<<1024, 256>>>(nbr_idx, nbr_mask, K2 * n);
    xh_kernel<<<512, 256>>>(x, n);
    wcvt_kernel<<<(K2 * COUT * COUT + 255) / 256, 256>>>(W1, W2, Wp);

    int blocks = (n + 511) / 512;
    conv1_kernel<<<blocks, 256, smem1>>>(b1, n);
    conv2_kernel<<<blocks, 256, smem2>>>(b2, bp, out, n);
}

// round 13
// speedup vs baseline: 1.3569x; 1.3569x over previous
#include <cuda_runtime.h>
#include <cuda_fp16.h>
#include <cstdint>

#define CIN 16
#define COUT 32
#define K2 9
#define MAXN 2000000
#define WSTR 40    // weight SMEM row stride in halves (80 B)
#define AROW 80    // A-tile row stride bytes

// fp16 intermediate h1 (128 MB ~ L2-resident) and fp16 copy of x (64 MB).
__device__ __align__(256) __half g_h1h[(size_t)MAXN * COUT];
__device__ __align__(256) __half g_xh[(size_t)MAXN * CIN];
// fused gather index: cidx = mask ? idx : -1
__device__ int g_cidx[(size_t)K2 * MAXN];
// fp16 weights (compact)
__device__ __half g_w1h[K2 * CIN * COUT];
__device__ __half g_w2h[K2 * COUT * COUT];
__device__ __half g_wph[CIN * COUT];
// zero row (64 B) for masked / out-of-range gathers
__device__ __align__(64) unsigned g_zrow[16] = {};

// ---- PTX wrappers ----
__device__ __forceinline__ void ldg256(const void* p, uint4& a, uint4& b) {
    asm("ld.global.nc.v8.b32 {%0,%1,%2,%3,%4,%5,%6,%7}, [%8];"
        : "=r"(a.x), "=r"(a.y), "=r"(a.z), "=r"(a.w),
          "=r"(b.x), "=r"(b.y), "=r"(b.z), "=r"(b.w)
        : "l"(p));
}
__device__ __forceinline__ void ldsm4(unsigned r[4], unsigned addr) {
    asm volatile("ldmatrix.sync.aligned.m8n8.x4.shared.b16 {%0,%1,%2,%3}, [%4];"
                 : "=r"(r[0]), "=r"(r[1]), "=r"(r[2]), "=r"(r[3]) : "r"(addr));
}
__device__ __forceinline__ void ldsm4t(unsigned r[4], unsigned addr) {
    asm volatile("ldmatrix.sync.aligned.m8n8.x4.trans.shared.b16 {%0,%1,%2,%3}, [%4];"
                 : "=r"(r[0]), "=r"(r[1]), "=r"(r[2]), "=r"(r[3]) : "r"(addr));
}
__device__ __forceinline__ void mma16816(float c[4], const unsigned a[4],
                                         unsigned b0, unsigned b1) {
    asm("mma.sync.aligned.m16n8k16.row.col.f32.f16.f16.f32 "
        "{%0,%1,%2,%3}, {%4,%5,%6,%7}, {%8,%9}, {%0,%1,%2,%3};"
        : "+f"(c[0]), "+f"(c[1]), "+f"(c[2]), "+f"(c[3])
        : "r"(a[0]), "r"(a[1]), "r"(a[2]), "r"(a[3]), "r"(b0), "r"(b1));
}

// =====================================================================
// prologues
// =====================================================================
__global__ __launch_bounds__(256)
void fuse_kernel(const int* __restrict__ idx, const unsigned* __restrict__ mask, int total) {
    int i = blockIdx.x * blockDim.x + threadIdx.x;
    int stride = gridDim.x * blockDim.x;
    int t4 = total >> 2;
    const int4* i4 = (const int4*)idx;
    const uint4* m4 = (const uint4*)mask;
    int4* c4 = (int4*)g_cidx;
    for (int j = i; j < t4; j += stride) {
        int4 v = i4[j]; uint4 m = m4[j];
        v.x = m.x ? v.x : -1;  v.y = m.y ? v.y : -1;
        v.z = m.z ? v.z : -1;  v.w = m.w ? v.w : -1;
        c4[j] = v;
    }
    if (i == 0)
        for (int j = t4 * 4; j < total; j++) g_cidx[j] = mask[j] ? idx[j] : -1;
}

__global__ __launch_bounds__(256)
void xh_kernel(const float* __restrict__ x, int n) {
    int total8 = n * CIN / 8;
    int stride = gridDim.x * blockDim.x;
    const float4* x4 = (const float4*)x;
    uint4* o4 = (uint4*)g_xh;
    for (int j = blockIdx.x * blockDim.x + threadIdx.x; j < total8; j += stride) {
        float4 a = __ldg(x4 + 2 * j), b = __ldg(x4 + 2 * j + 1);
        uint4 o; __half2 h;
        h = __floats2half2_rn(a.x, a.y); o.x = *(unsigned*)&h;
        h = __floats2half2_rn(a.z, a.w); o.y = *(unsigned*)&h;
        h = __floats2half2_rn(b.x, b.y); o.z = *(unsigned*)&h;
        h = __floats2half2_rn(b.z, b.w); o.w = *(unsigned*)&h;
        o4[j] = o;
    }
}

__global__ __launch_bounds__(256)
void wcvt_kernel(const float* __restrict__ W1, const float* __restrict__ W2,
                 const float* __restrict__ Wp) {
    int i = blockIdx.x * 256 + threadIdx.x;
    if (i < K2 * CIN * COUT)  g_w1h[i] = __float2half(W1[i]);
    if (i < K2 * COUT * COUT) g_w2h[i] = __float2half(W2[i]);
    if (i < CIN * COUT)       g_wph[i] = __float2half(Wp[i]);
}

// =====================================================================
// conv1: h1(fp16) = relu( sum_k x_h[cidx] @ W1[k] + b1 )
// warp tile M=64; 5 super-rounds of K=32 (taps 2j,2j+1; tap 9 = zero wts).
// Register-staged LDG, single A-buffer, idx prefetched one round ahead.
// =====================================================================
__global__ __launch_bounds__(256, 2)
void conv1_kernel(const float* __restrict__ b1, int n) {
    extern __shared__ char smem[];
    __half* atile = (__half*)smem;                         // 8 warps * 64 * 80 B
    __half* wsm   = (__half*)(smem + 8 * 64 * AROW);       // 10 taps * 16 * WSTR
    float*  bsm   = (float*)(wsm + 10 * CIN * WSTR);

    const int t = threadIdx.x, lane = t & 31, w = t >> 5;
    for (int i = t; i < 10 * CIN * COUT; i += 256) {
        int row = i >> 5, cc = i & 31;
        wsm[row * WSTR + cc] = (i < K2 * CIN * COUT) ? g_w1h[i] : __float2half(0.f);
    }
    if (t < COUT) bsm[t] = __ldg(b1 + t);
    __syncthreads();

    const int grp = lane >> 2, tig = lane & 3;
    const int sub = lane & 7, ti = lane >> 3;
    const int v0w = blockIdx.x * 512 + w * 64;
    const int vA = v0w + lane, vB = vA + 32;

    char* arowA = (char*)atile + w * 64 * AROW + lane * AROW;
    char* arowB = arowA + 32 * AROW;
    const unsigned abase =
        (unsigned)__cvta_generic_to_shared((char*)atile + w * 64 * AROW);
    const unsigned wb0 = (unsigned)__cvta_generic_to_shared(wsm);
    const int lro = sub + ((ti & 1) << 3);
    const int lco = (ti >> 1) << 4;

    float acc[4][4][4];
#pragma unroll
    for (int m = 0; m < 4; m++)
#pragma unroll
        for (int nt = 0; nt < 4; nt++) {
            float c0 = bsm[8 * nt + 2 * tig], c1 = bsm[8 * nt + 2 * tig + 1];
            acc[m][nt][0] = c0; acc[m][nt][1] = c1;
            acc[m][nt][2] = c0; acc[m][nt][3] = c1;
        }

    // staging: supertap = 2 taps x 2 rows; 32 regs
    uint4 sA[4], sB[4];
    int4 inext;   // cidx for the NEXT supertap (A0,A1,B0,B1)

    auto load_idx = [&](int j) -> int4 {
        int k0 = 2 * j, k1 = 2 * j + 1;
        int4 r;
        r.x = (vA < n) ? __ldg(g_cidx + (size_t)k0 * n + vA) : -1;
        r.y = (k1 < K2 && vA < n) ? __ldg(g_cidx + (size_t)k1 * n + vA) : -1;
        r.z = (vB < n) ? __ldg(g_cidx + (size_t)k0 * n + vB) : -1;
        r.w = (k1 < K2 && vB < n) ? __ldg(g_cidx + (size_t)k1 * n + vB) : -1;
        return r;
    };
    auto load_rows = [&](int4 ci) {
        const void* pA0 = (ci.x >= 0) ? (const void*)(g_xh + (size_t)ci.x * CIN)
                                      : (const void*)g_zrow;
        const void* pA1 = (ci.y >= 0) ? (const void*)(g_xh + (size_t)ci.y * CIN)
                                      : (const void*)g_zrow;
        const void* pB0 = (ci.z >= 0) ? (const void*)(g_xh + (size_t)ci.z * CIN)
                                      : (const void*)g_zrow;
        const void* pB1 = (ci.w >= 0) ? (const void*)(g_xh + (size_t)ci.w * CIN)
                                      : (const void*)g_zrow;
        ldg256(pA0, sA[0], sA[1]);
        ldg256(pA1, sA[2], sA[3]);
        ldg256(pB0, sB[0], sB[1]);
        ldg256(pB1, sB[2], sB[3]);
    };

    load_rows(load_idx(0));
    inext = load_idx(1);

#pragma unroll
    for (int j = 0; j < 5; j++) {
        ((uint4*)arowA)[0] = sA[0];
        ((uint4*)arowA)[1] = sA[1];
        ((uint4*)arowA)[2] = sA[2];
        ((uint4*)arowA)[3] = sA[3];
        ((uint4*)arowB)[0] = sB[0];
        ((uint4*)arowB)[1] = sB[1];
        ((uint4*)arowB)[2] = sB[2];
        ((uint4*)arowB)[3] = sB[3];
        __syncwarp();
        if (j + 1 < 5) load_rows(inext);       // idx already resolved
        if (j + 2 < 5) inext = load_idx(j + 2);
        unsigned wtap = wb0 + j * (32 * WSTR * 2);
#pragma unroll
        for (int kt = 0; kt < 2; kt++) {
            unsigned bw[8];
            unsigned wk = wtap + (16 * kt + lro) * (WSTR * 2) + lco;
            ldsm4t(bw,     wk);
            ldsm4t(bw + 4, wk + 32);
#pragma unroll
            for (int m = 0; m < 4; m++) {
                unsigned av[4];
                ldsm4(av, abase + (16 * m + lro) * AROW + kt * 32 + lco);
                mma16816(acc[m][0], av, bw[0], bw[1]);
                mma16816(acc[m][1], av, bw[2], bw[3]);
                mma16816(acc[m][2], av, bw[4], bw[5]);
                mma16816(acc[m][3], av, bw[6], bw[7]);
            }
        }
        __syncwarp();
    }

    // epilogue: relu -> fp16 h1
#pragma unroll
    for (int m = 0; m < 4; m++) {
        int vg0 = v0w + 16 * m + grp, vg1 = vg0 + 8;
#pragma unroll
        for (int nt = 0; nt < 4; nt++) {
            const float* a = acc[m][nt];
            if (vg0 < n) {
                __half2 h = __floats2half2_rn(fmaxf(a[0], 0.f), fmaxf(a[1], 0.f));
                *(__half2*)(g_h1h + (size_t)vg0 * COUT + 8 * nt + 2 * tig) = h;
            }
            if (vg1 < n) {
                __half2 h = __floats2half2_rn(fmaxf(a[2], 0.f), fmaxf(a[3], 0.f));
                *(__half2*)(g_h1h + (size_t)vg1 * COUT + 8 * nt + 2 * tig) = h;
            }
        }
    }
}

// =====================================================================
// conv2 + residual: out = relu( sum_k h1[cidx] @ W2[k] + x_h @ Wp + b2 + bp )
// warp tile M=64, 9 taps K=32; register staging; idx prefetched 2 ahead.
// =====================================================================
__global__ __launch_bounds__(256, 2)
void conv2_kernel(const float* __restrict__ b2, const float* __restrict__ bp,
                  float* __restrict__ out, int n) {
    extern __shared__ char smem[];
    __half* atile = (__half*)smem;                          // 8 * 64 * 80 B
    __half* wsm   = (__half*)(smem + 8 * 64 * AROW);        // 9*32*WSTR
    __half* wpsm  = wsm + K2 * COUT * WSTR;                 // 16*WSTR
    float*  bsm   = (float*)(wpsm + CIN * WSTR);

    const int t = threadIdx.x, lane = t & 31, w = t >> 5;
    for (int i = t; i < K2 * COUT * COUT; i += 256) {
        int row = i >> 5, cc = i & 31;
        wsm[row * WSTR + cc] = g_w2h[i];
    }
    for (int i = t; i < CIN * COUT; i += 256) {
        int row = i >> 5, cc = i & 31;
        wpsm[row * WSTR + cc] = g_wph[i];
    }
    if (t < COUT) bsm[t] = __ldg(b2 + t) + __ldg(bp + t);
    __syncthreads();

    const int grp = lane >> 2, tig = lane & 3;
    const int sub = lane & 7, ti = lane >> 3;
    const int v0w = blockIdx.x * 512 + w * 64;
    const int vA = v0w + lane, vB = vA + 32;

    char* arowA = (char*)atile + w * 64 * AROW + lane * AROW;
    char* arowB = arowA + 32 * AROW;
    const unsigned abase =
        (unsigned)__cvta_generic_to_shared((char*)atile + w * 64 * AROW);
    const unsigned wb0 = (unsigned)__cvta_generic_to_shared(wsm);
    const unsigned wpb = (unsigned)__cvta_generic_to_shared(wpsm);
    const int lro = sub + ((ti & 1) << 3);
    const int lco = (ti >> 1) << 4;

    float acc[4][4][4];
#pragma unroll
    for (int m = 0; m < 4; m++)
#pragma unroll
        for (int nt = 0; nt < 4; nt++) {
            float c0 = bsm[8 * nt + 2 * tig], c1 = bsm[8 * nt + 2 * tig + 1];
            acc[m][nt][0] = c0; acc[m][nt][1] = c1;
            acc[m][nt][2] = c0; acc[m][nt][3] = c1;
        }

    uint4 sA[4], sB[4];
    int2 inext;   // cidx for next tap (A,B)

    auto load_idx = [&](int k) -> int2 {
        int2 r;
        r.x = (vA < n) ? __ldg(g_cidx + (size_t)k * n + vA) : -1;
        r.y = (vB < n) ? __ldg(g_cidx + (size_t)k * n + vB) : -1;
        return r;
    };
    auto load_rows = [&](int2 ci) {
        const char* pA = (ci.x >= 0) ? (const char*)(g_h1h + (size_t)ci.x * COUT)
                                     : (const char*)g_zrow;
        const char* pB = (ci.y >= 0) ? (const char*)(g_h1h + (size_t)ci.y * COUT)
                                     : (const char*)g_zrow;
        ldg256(pA,      sA[0], sA[1]);
        ldg256(pA + 32, sA[2], sA[3]);
        ldg256(pB,      sB[0], sB[1]);
        ldg256(pB + 32, sB[2], sB[3]);
    };

    // ---- projection tap (K=16) from own fp16 x rows ----
    {
        uint4 p0, p1;
        if (vA < n) ldg256(g_xh + (size_t)vA * CIN, p0, p1);
        else { p0 = make_uint4(0, 0, 0, 0); p1 = p0; }
        ((uint4*)arowA)[0] = p0; ((uint4*)arowA)[1] = p1;
        if (vB < n) ldg256(g_xh + (size_t)vB * CIN, p0, p1);
        else { p0 = make_uint4(0, 0, 0, 0); p1 = p0; }
        ((uint4*)arowB)[0] = p0; ((uint4*)arowB)[1] = p1;
        __syncwarp();
    }

    // start gather pipeline (overlaps proj MMA)
    load_rows(load_idx(0));
    inext = load_idx(1);

    // proj MMA (K=16)
    {
        unsigned bw[8];
        unsigned wp0 = wpb + lro * (WSTR * 2) + lco;
        ldsm4t(bw,     wp0);
        ldsm4t(bw + 4, wp0 + 32);
#pragma unroll
        for (int m = 0; m < 4; m++) {
            unsigned av[4];
            ldsm4(av, abase + (16 * m + lro) * AROW + lco);
            mma16816(acc[m][0], av, bw[0], bw[1]);
            mma16816(acc[m][1], av, bw[2], bw[3]);
            mma16816(acc[m][2], av, bw[4], bw[5]);
            mma16816(acc[m][3], av, bw[6], bw[7]);
        }
        __syncwarp();
    }

    // ---- 9 conv taps (K=32) ----
#pragma unroll
    for (int k = 0; k < K2; k++) {
        ((uint4*)arowA)[0] = sA[0];
        ((uint4*)arowA)[1] = sA[1];
        ((uint4*)arowA)[2] = sA[2];
        ((uint4*)arowA)[3] = sA[3];
        ((uint4*)arowB)[0] = sB[0];
        ((uint4*)arowB)[1] = sB[1];
        ((uint4*)arowB)[2] = sB[2];
        ((uint4*)arowB)[3] = sB[3];
        __syncwarp();
        if (k + 1 < K2) load_rows(inext);      // idx already resolved
        if (k + 2 < K2) inext = load_idx(k + 2);
        unsigned wtap = wb0 + k * (COUT * WSTR * 2);
#pragma unroll
        for (int kt = 0; kt < 2; kt++) {
            unsigned bw[8];
            unsigned wk = wtap + (16 * kt + lro) * (WSTR * 2) + lco;
            ldsm4t(bw,     wk);
            ldsm4t(bw + 4, wk + 32);
#pragma unroll
            for (int m = 0; m < 4; m++) {
                unsigned av[4];
                ldsm4(av, abase + (16 * m + lro) * AROW + kt * 32 + lco);
                mma16816(acc[m][0], av, bw[0], bw[1]);
                mma16816(acc[m][1], av, bw[2], bw[3]);
                mma16816(acc[m][2], av, bw[4], bw[5]);
                mma16816(acc[m][3], av, bw[6], bw[7]);
            }
        }
        __syncwarp();
    }

    // epilogue: relu -> fp32 out
#pragma unroll
    for (int m = 0; m < 4; m++) {
        int vg0 = v0w + 16 * m + grp, vg1 = vg0 + 8;
#pragma unroll
        for (int nt = 0; nt < 4; nt++) {
            const float* a = acc[m][nt];
            if (vg0 < n)
                *(float2*)(out + (size_t)vg0 * COUT + 8 * nt + 2 * tig) =
                    make_float2(fmaxf(a[0], 0.f), fmaxf(a[1], 0.f));
            if (vg1 < n)
                *(float2*)(out + (size_t)vg1 * COUT + 8 * nt + 2 * tig) =
                    make_float2(fmaxf(a[2], 0.f), fmaxf(a[3], 0.f));
        }
    }
}

// =====================================================================
// Launch.  Input order: x, W1, b1, W2, b2, Wp, bp, nbr_idx, nbr_mask
// =====================================================================
extern "C" void kernel_launch(void* const* d_in, const int* in_sizes, int n_in,
                              void* d_out, int out_size) {
    const float* x  = (const float*)d_in[0];
    const float* W1 = (const float*)d_in[1];
    const float* b1 = (const float*)d_in[2];
    const float* W2 = (const float*)d_in[3];
    const float* b2 = (const float*)d_in[4];
    const float* Wp = (const float*)d_in[5];
    const float* bp = (const float*)d_in[6];
    const int* nbr_idx = (const int*)d_in[7];
    const unsigned* nbr_mask = (const unsigned*)d_in[8];
    float* out = (float*)d_out;

    int n = in_sizes[0] / CIN;
    if (n > MAXN) n = MAXN;

    const int smem1 = 8 * 64 * AROW + 10 * CIN * WSTR * 2 + COUT * 4;
    const int smem2 = 8 * 64 * AROW + K2 * COUT * WSTR * 2 + CIN * WSTR * 2 + COUT * 4;
    cudaFuncSetAttribute(conv1_kernel, cudaFuncAttributeMaxDynamicSharedMemorySize, smem1);
    cudaFuncSetAttribute(conv2_kernel, cudaFuncAttributeMaxDynamicSharedMemorySize, smem2);

    fuse_kernel<<<1024, 256>>>(nbr_idx, nbr_mask, K2 * n);
    xh_kernel<<<512, 256>>>(x, n);
    wcvt_kernel<<<(K2 * COUT * COUT + 255) / 256, 256>>>(W1, W2, Wp);

    int blocks = (n + 511) / 512;
    conv1_kernel<<<blocks, 256, smem1>>>(b1, n);
    conv2_kernel<<<blocks, 256, smem2>>>(b2, bp, out, n);
}

// round 14
// speedup vs baseline: 1.4386x; 1.0602x over previous
#include <cuda_runtime.h>
#include <cuda_fp16.h>
#include <cstdint>

#define CIN 16
#define COUT 32
#define K2 9
#define MAXN 2000000
#define WSTR 40    // weight SMEM row stride in halves (80 B)
#define A1B 48     // conv1 A-tile row stride bytes
#define AROW 80    // conv2 A-tile row stride bytes

// fp16 intermediate h1 (128 MB ~ L2-resident) and fp16 copy of x (64 MB).
__device__ __align__(256) __half g_h1h[(size_t)MAXN * COUT];
__device__ __align__(256) __half g_xh[(size_t)MAXN * CIN];
// fused gather index: cidx = mask ? idx : -1
__device__ int g_cidx[(size_t)K2 * MAXN];
// fp16 weights (compact)
__device__ __half g_w1h[K2 * CIN * COUT];
__device__ __half g_w2h[K2 * COUT * COUT];
__device__ __half g_wph[CIN * COUT];
// zero row (64 B) for masked / out-of-range gathers
__device__ __align__(64) unsigned g_zrow[16] = {};

// ---- PTX wrappers ----
__device__ __forceinline__ void ldg256(const void* p, uint4& a, uint4& b) {
    asm("ld.global.nc.v8.b32 {%0,%1,%2,%3,%4,%5,%6,%7}, [%8];"
        : "=r"(a.x), "=r"(a.y), "=r"(a.z), "=r"(a.w),
          "=r"(b.x), "=r"(b.y), "=r"(b.z), "=r"(b.w)
        : "l"(p));
}
__device__ __forceinline__ void ldsm4(unsigned r[4], unsigned addr) {
    asm volatile("ldmatrix.sync.aligned.m8n8.x4.shared.b16 {%0,%1,%2,%3}, [%4];"
                 : "=r"(r[0]), "=r"(r[1]), "=r"(r[2]), "=r"(r[3]) : "r"(addr));
}
__device__ __forceinline__ void ldsm4t(unsigned r[4], unsigned addr) {
    asm volatile("ldmatrix.sync.aligned.m8n8.x4.trans.shared.b16 {%0,%1,%2,%3}, [%4];"
                 : "=r"(r[0]), "=r"(r[1]), "=r"(r[2]), "=r"(r[3]) : "r"(addr));
}
__device__ __forceinline__ void mma16816(float c[4], const unsigned a[4],
                                         unsigned b0, unsigned b1) {
    asm("mma.sync.aligned.m16n8k16.row.col.f32.f16.f16.f32 "
        "{%0,%1,%2,%3}, {%4,%5,%6,%7}, {%8,%9}, {%0,%1,%2,%3};"
        : "+f"(c[0]), "+f"(c[1]), "+f"(c[2]), "+f"(c[3])
        : "r"(a[0]), "r"(a[1]), "r"(a[2]), "r"(a[3]), "r"(b0), "r"(b1));
}

// =====================================================================
// prologues
// =====================================================================
__global__ __launch_bounds__(256)
void fuse_kernel(const int* __restrict__ idx, const unsigned* __restrict__ mask, int total) {
    int i = blockIdx.x * blockDim.x + threadIdx.x;
    int stride = gridDim.x * blockDim.x;
    int t4 = total >> 2;
    const int4* i4 = (const int4*)idx;
    const uint4* m4 = (const uint4*)mask;
    int4* c4 = (int4*)g_cidx;
    for (int j = i; j < t4; j += stride) {
        int4 v = i4[j]; uint4 m = m4[j];
        v.x = m.x ? v.x : -1;  v.y = m.y ? v.y : -1;
        v.z = m.z ? v.z : -1;  v.w = m.w ? v.w : -1;
        c4[j] = v;
    }
    if (i == 0)
        for (int j = t4 * 4; j < total; j++) g_cidx[j] = mask[j] ? idx[j] : -1;
}

__global__ __launch_bounds__(256)
void xh_kernel(const float* __restrict__ x, int n) {
    int total8 = n * CIN / 8;
    int stride = gridDim.x * blockDim.x;
    const float4* x4 = (const float4*)x;
    uint4* o4 = (uint4*)g_xh;
    for (int j = blockIdx.x * blockDim.x + threadIdx.x; j < total8; j += stride) {
        float4 a = __ldg(x4 + 2 * j), b = __ldg(x4 + 2 * j + 1);
        uint4 o; __half2 h;
        h = __floats2half2_rn(a.x, a.y); o.x = *(unsigned*)&h;
        h = __floats2half2_rn(a.z, a.w); o.y = *(unsigned*)&h;
        h = __floats2half2_rn(b.x, b.y); o.z = *(unsigned*)&h;
        h = __floats2half2_rn(b.z, b.w); o.w = *(unsigned*)&h;
        o4[j] = o;
    }
}

__global__ __launch_bounds__(256)
void wcvt_kernel(const float* __restrict__ W1, const float* __restrict__ W2,
                 const float* __restrict__ Wp) {
    int i = blockIdx.x * 256 + threadIdx.x;
    if (i < K2 * CIN * COUT)  g_w1h[i] = __float2half(W1[i]);
    if (i < K2 * COUT * COUT) g_w2h[i] = __float2half(W2[i]);
    if (i < CIN * COUT)       g_wph[i] = __float2half(Wp[i]);
}

// =====================================================================
// conv1 (R11 version): warp tile M=64 (2 rows/lane), depth-2 prefetch.
// =====================================================================
__global__ __launch_bounds__(256, 2)
void conv1_kernel(const float* __restrict__ b1, int n) {
    __shared__ __half wsm[K2 * CIN * WSTR];                     // 11.5 KB
    __shared__ float bsm[COUT];
    __shared__ __align__(16) __half atile[8 * 64 * (A1B / 2)];  // 24 KB

    const int t = threadIdx.x, lane = t & 31, w = t >> 5;
    for (int i = t; i < K2 * CIN * COUT; i += 256) {
        int row = i >> 5, cc = i & 31;
        wsm[row * WSTR + cc] = g_w1h[i];
    }
    if (t < COUT) bsm[t] = __ldg(b1 + t);
    __syncthreads();

    const int grp = lane >> 2, tig = lane & 3;
    const int sub = lane & 7, ti = lane >> 3;
    const int v0w = blockIdx.x * 512 + w * 64;
    const int vA = v0w + lane, vB = vA + 32;

    char* arowA = (char*)atile + w * 64 * A1B + lane * A1B;
    char* arowB = arowA + 32 * A1B;
    const unsigned abase =
        (unsigned)__cvta_generic_to_shared((char*)atile + w * 64 * A1B);
    const unsigned wb0 = (unsigned)__cvta_generic_to_shared(wsm);
    const int lro = sub + ((ti & 1) << 3);
    const int lco = (ti >> 1) << 4;

    float acc[4][4][4];
#pragma unroll
    for (int m = 0; m < 4; m++)
#pragma unroll
        for (int nt = 0; nt < 4; nt++) {
            float c0 = bsm[8 * nt + 2 * tig], c1 = bsm[8 * nt + 2 * tig + 1];
            acc[m][nt][0] = c0; acc[m][nt][1] = c1;
            acc[m][nt][2] = c0; acc[m][nt][3] = c1;
        }

    uint4 gA[2][2], gB[2][2];
    auto load1 = [&](int k, int buf) {
        int ciA = (vA < n) ? __ldg(g_cidx + (size_t)k * n + vA) : -1;
        int ciB = (vB < n) ? __ldg(g_cidx + (size_t)k * n + vB) : -1;
        const void* pA = (ciA >= 0) ? (const void*)(g_xh + (size_t)ciA * CIN)
                                    : (const void*)g_zrow;
        const void* pB = (ciB >= 0) ? (const void*)(g_xh + (size_t)ciB * CIN)
                                    : (const void*)g_zrow;
        ldg256(pA, gA[buf][0], gA[buf][1]);
        ldg256(pB, gB[buf][0], gB[buf][1]);
    };

    load1(0, 0);
    load1(1, 1);

#pragma unroll
    for (int k = 0; k < K2; k++) {
        int cur = k & 1;
        ((uint4*)arowA)[0] = gA[cur][0];
        ((uint4*)arowA)[1] = gA[cur][1];
        ((uint4*)arowB)[0] = gB[cur][0];
        ((uint4*)arowB)[1] = gB[cur][1];
        __syncwarp();
        if (k + 2 < K2) load1(k + 2, cur);
        unsigned bw[8];
        unsigned wtap = wb0 + k * (CIN * WSTR * 2) + lro * (WSTR * 2) + lco;
        ldsm4t(bw,     wtap);
        ldsm4t(bw + 4, wtap + 32);
#pragma unroll
        for (int m = 0; m < 4; m++) {
            unsigned av[4];
            ldsm4(av, abase + (16 * m + lro) * A1B + lco);
            mma16816(acc[m][0], av, bw[0], bw[1]);
            mma16816(acc[m][1], av, bw[2], bw[3]);
            mma16816(acc[m][2], av, bw[4], bw[5]);
            mma16816(acc[m][3], av, bw[6], bw[7]);
        }
        __syncwarp();
    }

    // epilogue: relu -> fp16 h1
#pragma unroll
    for (int m = 0; m < 4; m++) {
        int vg0 = v0w + 16 * m + grp, vg1 = vg0 + 8;
#pragma unroll
        for (int nt = 0; nt < 4; nt++) {
            const float* a = acc[m][nt];
            if (vg0 < n) {
                __half2 h = __floats2half2_rn(fmaxf(a[0], 0.f), fmaxf(a[1], 0.f));
                *(__half2*)(g_h1h + (size_t)vg0 * COUT + 8 * nt + 2 * tig) = h;
            }
            if (vg1 < n) {
                __half2 h = __floats2half2_rn(fmaxf(a[2], 0.f), fmaxf(a[3], 0.f));
                *(__half2*)(g_h1h + (size_t)vg1 * COUT + 8 * nt + 2 * tig) = h;
            }
        }
    }
}

// =====================================================================
// conv2 + residual: warp tile M=64, 9 taps K=32.
// PAIR-COOPERATIVE gathers: 2 lanes per 64B h1 row -> 16 lines per
// LDG.256 instruction (half the L1 wavefronts). idx prefetched 1 tap ahead.
// =====================================================================
__global__ __launch_bounds__(256, 2)
void conv2_kernel(const float* __restrict__ b2, const float* __restrict__ bp,
                  float* __restrict__ out, int n) {
    extern __shared__ char smem[];
    __half* atile = (__half*)smem;                          // 8 * 64 * 80 B
    __half* wsm   = (__half*)(smem + 8 * 64 * AROW);        // 9*32*WSTR
    __half* wpsm  = wsm + K2 * COUT * WSTR;                 // 16*WSTR
    float*  bsm   = (float*)(wpsm + CIN * WSTR);

    const int t = threadIdx.x, lane = t & 31, w = t >> 5;
    for (int i = t; i < K2 * COUT * COUT; i += 256) {
        int row = i >> 5, cc = i & 31;
        wsm[row * WSTR + cc] = g_w2h[i];
    }
    for (int i = t; i < CIN * COUT; i += 256) {
        int row = i >> 5, cc = i & 31;
        wpsm[row * WSTR + cc] = g_wph[i];
    }
    if (t < COUT) bsm[t] = __ldg(b2 + t) + __ldg(bp + t);
    __syncthreads();

    const int grp = lane >> 2, tig = lane & 3;
    const int sub = lane & 7, ti = lane >> 3;
    const int v0w = blockIdx.x * 512 + w * 64;
    const int vA = v0w + lane, vB = vA + 32;

    // pair-cooperative gather mapping: lane pair (2i,2i+1) covers one row
    const int prow = lane >> 1;      // 0..15 : row within 16-row segment
    const int phalf = lane & 1;      // which 32B half of the 64B row

    char* atw = (char*)atile + w * 64 * AROW;
    char* arowA = atw + lane * AROW;
    char* arowB = arowA + 32 * AROW;
    const unsigned abase = (unsigned)__cvta_generic_to_shared(atw);
    const unsigned wb0 = (unsigned)__cvta_generic_to_shared(wsm);
    const unsigned wpb = (unsigned)__cvta_generic_to_shared(wpsm);
    const int lro = sub + ((ti & 1) << 3);
    const int lco = (ti >> 1) << 4;

    float acc[4][4][4];
#pragma unroll
    for (int m = 0; m < 4; m++)
#pragma unroll
        for (int nt = 0; nt < 4; nt++) {
            float c0 = bsm[8 * nt + 2 * tig], c1 = bsm[8 * nt + 2 * tig + 1];
            acc[m][nt][0] = c0; acc[m][nt][1] = c1;
            acc[m][nt][2] = c0; acc[m][nt][3] = c1;
        }

    // staging: 4 segments x 32B per lane = 32 regs
    uint4 s[4][2];
    int4 inext;    // per-segment cidx for the NEXT tap

    auto load_idx = [&](int k) -> int4 {
        int4 r;
#pragma unroll
        for (int seg = 0; seg < 4; seg++) {
            int vx = v0w + seg * 16 + prow;
            ((int*)&r)[seg] = (vx < n) ? __ldg(g_cidx + (size_t)k * n + vx) : -1;
        }
        return r;
    };
    auto load_rows = [&](int4 ci) {
#pragma unroll
        for (int seg = 0; seg < 4; seg++) {
            int c = ((const int*)&ci)[seg];
            const char* p = (c >= 0) ? (const char*)(g_h1h + (size_t)c * COUT)
                                     : (const char*)g_zrow;
            ldg256(p + phalf * 32, s[seg][0], s[seg][1]);
        }
    };
    auto sts_rows = [&]() {
#pragma unroll
        for (int seg = 0; seg < 4; seg++) {
            char* d = atw + (seg * 16 + prow) * AROW + phalf * 32;
            ((uint4*)d)[0] = s[seg][0];
            ((uint4*)d)[1] = s[seg][1];
        }
    };

    // ---- projection tap (K=16) from own fp16 x rows (coalesced) ----
    {
        uint4 p0, p1;
        if (vA < n) ldg256(g_xh + (size_t)vA * CIN, p0, p1);
        else { p0 = make_uint4(0, 0, 0, 0); p1 = p0; }
        ((uint4*)arowA)[0] = p0; ((uint4*)arowA)[1] = p1;
        if (vB < n) ldg256(g_xh + (size_t)vB * CIN, p0, p1);
        else { p0 = make_uint4(0, 0, 0, 0); p1 = p0; }
        ((uint4*)arowB)[0] = p0; ((uint4*)arowB)[1] = p1;
        __syncwarp();
    }

    // start gather pipeline (overlaps proj MMA)
    load_rows(load_idx(0));
    inext = load_idx(1);

    // proj MMA (K=16)
    {
        unsigned bw[8];
        unsigned wp0 = wpb + lro * (WSTR * 2) + lco;
        ldsm4t(bw,     wp0);
        ldsm4t(bw + 4, wp0 + 32);
#pragma unroll
        for (int m = 0; m < 4; m++) {
            unsigned av[4];
            ldsm4(av, abase + (16 * m + lro) * AROW + lco);
            mma16816(acc[m][0], av, bw[0], bw[1]);
            mma16816(acc[m][1], av, bw[2], bw[3]);
            mma16816(acc[m][2], av, bw[4], bw[5]);
            mma16816(acc[m][3], av, bw[6], bw[7]);
        }
        __syncwarp();
    }

    // ---- 9 conv taps (K=32) ----
#pragma unroll
    for (int k = 0; k < K2; k++) {
        sts_rows();
        __syncwarp();
        if (k + 1 < K2) load_rows(inext);      // idx already resolved
        if (k + 2 < K2) inext = load_idx(k + 2);
        unsigned wtap = wb0 + k * (COUT * WSTR * 2);
#pragma unroll
        for (int kt = 0; kt < 2; kt++) {
            unsigned bw[8];
            unsigned wk = wtap + (16 * kt + lro) * (WSTR * 2) + lco;
            ldsm4t(bw,     wk);
            ldsm4t(bw + 4, wk + 32);
#pragma unroll
            for (int m = 0; m < 4; m++) {
                unsigned av[4];
                ldsm4(av, abase + (16 * m + lro) * AROW + kt * 32 + lco);
                mma16816(acc[m][0], av, bw[0], bw[1]);
                mma16816(acc[m][1], av, bw[2], bw[3]);
                mma16816(acc[m][2], av, bw[4], bw[5]);
                mma16816(acc[m][3], av, bw[6], bw[7]);
            }
        }
        __syncwarp();
    }

    // epilogue: relu -> fp32 out
#pragma unroll
    for (int m = 0; m < 4; m++) {
        int vg0 = v0w + 16 * m + grp, vg1 = vg0 + 8;
#pragma unroll
        for (int nt = 0; nt < 4; nt++) {
            const float* a = acc[m][nt];
            if (vg0 < n)
                *(float2*)(out + (size_t)vg0 * COUT + 8 * nt + 2 * tig) =
                    make_float2(fmaxf(a[0], 0.f), fmaxf(a[1], 0.f));
            if (vg1 < n)
                *(float2*)(out + (size_t)vg1 * COUT + 8 * nt + 2 * tig) =
                    make_float2(fmaxf(a[2], 0.f), fmaxf(a[3], 0.f));
        }
    }
}

// =====================================================================
// Launch.  Input order: x, W1, b1, W2, b2, Wp, bp, nbr_idx, nbr_mask
// =====================================================================
extern "C" void kernel_launch(void* const* d_in, const int* in_sizes, int n_in,
                              void* d_out, int out_size) {
    const float* x  = (const float*)d_in[0];
    const float* W1 = (const float*)d_in[1];
    const float* b1 = (const float*)d_in[2];
    const float* W2 = (const float*)d_in[3];
    const float* b2 = (const float*)d_in[4];
    const float* Wp = (const float*)d_in[5];
    const float* bp = (const float*)d_in[6];
    const int* nbr_idx = (const int*)d_in[7];
    const unsigned* nbr_mask = (const unsigned*)d_in[8];
    float* out = (float*)d_out;

    int n = in_sizes[0] / CIN;
    if (n > MAXN) n = MAXN;

    const int smem2 = 8 * 64 * AROW + K2 * COUT * WSTR * 2 + CIN * WSTR * 2 + COUT * 4;
    cudaFuncSetAttribute(conv2_kernel, cudaFuncAttributeMaxDynamicSharedMemorySize, smem2);

    fuse_kernel<<<1024, 256>>>(nbr_idx, nbr_mask, K2 * n);
    xh_kernel<<<512, 256>>>(x, n);
    wcvt_kernel<<<(K2 * COUT * COUT + 255) / 256, 256>>>(W1, W2, Wp);

    int blocks = (n + 511) / 512;
    conv1_kernel<<<blocks, 256>>>(b1, n);
    conv2_kernel<<<blocks, 256, smem2>>>(b2, bp, out, n);
}

// round 15
// speedup vs baseline: 1.4458x; 1.0050x over previous
#include <cuda_runtime.h>
#include <cuda_fp16.h>
#include <cstdint>

#define CIN 16
#define COUT 32
#define K2 9
#define MAXN 2000000
#define WSTR 40    // weight SMEM row stride in halves (80 B)
#define A1B 48     // conv1 A-tile row stride bytes
#define AROW 80    // conv2 A-tile row stride bytes

// fp16 intermediate h1 (128 MB ~ L2-resident) and fp16 copy of x (64 MB).
__device__ __align__(256) __half g_h1h[(size_t)MAXN * COUT];
__device__ __align__(256) __half g_xh[(size_t)MAXN * CIN];
// fp16 weights (compact)
__device__ __half g_w1h[K2 * CIN * COUT];
__device__ __half g_w2h[K2 * COUT * COUT];
__device__ __half g_wph[CIN * COUT];
// zero row (64 B) for masked / out-of-range gathers
__device__ __align__(64) unsigned g_zrow[16] = {};

// ---- PTX wrappers ----
__device__ __forceinline__ void ldg256(const void* p, uint4& a, uint4& b) {
    asm("ld.global.nc.v8.b32 {%0,%1,%2,%3,%4,%5,%6,%7}, [%8];"
        : "=r"(a.x), "=r"(a.y), "=r"(a.z), "=r"(a.w),
          "=r"(b.x), "=r"(b.y), "=r"(b.z), "=r"(b.w)
        : "l"(p));
}
__device__ __forceinline__ void ldsm4(unsigned r[4], unsigned addr) {
    asm volatile("ldmatrix.sync.aligned.m8n8.x4.shared.b16 {%0,%1,%2,%3}, [%4];"
                 : "=r"(r[0]), "=r"(r[1]), "=r"(r[2]), "=r"(r[3]) : "r"(addr));
}
__device__ __forceinline__ void ldsm4t(unsigned r[4], unsigned addr) {
    asm volatile("ldmatrix.sync.aligned.m8n8.x4.trans.shared.b16 {%0,%1,%2,%3}, [%4];"
                 : "=r"(r[0]), "=r"(r[1]), "=r"(r[2]), "=r"(r[3]) : "r"(addr));
}
__device__ __forceinline__ void mma16816(float c[4], const unsigned a[4],
                                         unsigned b0, unsigned b1) {
    asm("mma.sync.aligned.m16n8k16.row.col.f32.f16.f16.f32 "
        "{%0,%1,%2,%3}, {%4,%5,%6,%7}, {%8,%9}, {%0,%1,%2,%3};"
        : "+f"(c[0]), "+f"(c[1]), "+f"(c[2]), "+f"(c[3])
        : "r"(a[0]), "r"(a[1]), "r"(a[2]), "r"(a[3]), "r"(b0), "r"(b1));
}
// mask folded into index without a branch
__device__ __forceinline__ int sel_idx(int ix, unsigned mk) {
    int r;
    asm("{ .reg .pred p; setp.ne.u32 p, %1, 0; selp.b32 %0, %2, -1, p; }"
        : "=r"(r) : "r"(mk), "r"(ix));
    return r;
}

// =====================================================================
// merged prologue: x -> fp16 copy  +  weights -> fp16
// =====================================================================
__global__ __launch_bounds__(256)
void xhw_kernel(const float* __restrict__ x,
                const float* __restrict__ W1, const float* __restrict__ W2,
                const float* __restrict__ Wp, int n) {
    int gid = blockIdx.x * blockDim.x + threadIdx.x;
    int stride = gridDim.x * blockDim.x;
    int total8 = n * CIN / 8;
    const float4* x4 = (const float4*)x;
    uint4* o4 = (uint4*)g_xh;
    for (int j = gid; j < total8; j += stride) {
        float4 a = __ldg(x4 + 2 * j), b = __ldg(x4 + 2 * j + 1);
        uint4 o; __half2 h;
        h = __floats2half2_rn(a.x, a.y); o.x = *(unsigned*)&h;
        h = __floats2half2_rn(a.z, a.w); o.y = *(unsigned*)&h;
        h = __floats2half2_rn(b.x, b.y); o.z = *(unsigned*)&h;
        h = __floats2half2_rn(b.z, b.w); o.w = *(unsigned*)&h;
        o4[j] = o;
    }
    if (gid < K2 * COUT * COUT) {
        if (gid < K2 * CIN * COUT) g_w1h[gid] = __float2half(W1[gid]);
        g_w2h[gid] = __float2half(W2[gid]);
        if (gid < CIN * COUT) g_wph[gid] = __float2half(Wp[gid]);
    }
}

// =====================================================================
// conv1: h1(fp16) = relu( sum_k x_h[idx] @ W1[k] + b1 )   (mask inline)
// warp tile M=64 (2 rows/lane), rows depth-2, idx prefetched 1 further.
// =====================================================================
__global__ __launch_bounds__(256, 2)
void conv1_kernel(const int* __restrict__ nbr_idx,
                  const unsigned* __restrict__ nbr_mask,
                  const float* __restrict__ b1, int n) {
    __shared__ __half wsm[K2 * CIN * WSTR];                     // 11.5 KB
    __shared__ float bsm[COUT];
    __shared__ __align__(16) __half atile[8 * 64 * (A1B / 2)];  // 24 KB

    const int t = threadIdx.x, lane = t & 31, w = t >> 5;
    for (int i = t; i < K2 * CIN * COUT; i += 256) {
        int row = i >> 5, cc = i & 31;
        wsm[row * WSTR + cc] = g_w1h[i];
    }
    if (t < COUT) bsm[t] = __ldg(b1 + t);
    __syncthreads();

    const int grp = lane >> 2, tig = lane & 3;
    const int sub = lane & 7, ti = lane >> 3;
    const int v0w = blockIdx.x * 512 + w * 64;
    const int vA = v0w + lane, vB = vA + 32;

    char* arowA = (char*)atile + w * 64 * A1B + lane * A1B;
    char* arowB = arowA + 32 * A1B;
    const unsigned abase =
        (unsigned)__cvta_generic_to_shared((char*)atile + w * 64 * A1B);
    const unsigned wb0 = (unsigned)__cvta_generic_to_shared(wsm);
    const int lro = sub + ((ti & 1) << 3);
    const int lco = (ti >> 1) << 4;

    float acc[4][4][4];
#pragma unroll
    for (int m = 0; m < 4; m++)
#pragma unroll
        for (int nt = 0; nt < 4; nt++) {
            float c0 = bsm[8 * nt + 2 * tig], c1 = bsm[8 * nt + 2 * tig + 1];
            acc[m][nt][0] = c0; acc[m][nt][1] = c1;
            acc[m][nt][2] = c0; acc[m][nt][3] = c1;
        }

    auto load_idx = [&](int k) -> int2 {
        int2 r; r.x = -1; r.y = -1;
        if (vA < n) {
            int ix = __ldg(nbr_idx + (size_t)k * n + vA);
            unsigned mk = __ldg(nbr_mask + (size_t)k * n + vA);
            r.x = sel_idx(ix, mk);
        }
        if (vB < n) {
            int ix = __ldg(nbr_idx + (size_t)k * n + vB);
            unsigned mk = __ldg(nbr_mask + (size_t)k * n + vB);
            r.y = sel_idx(ix, mk);
        }
        return r;
    };

    uint4 gA[2][2], gB[2][2];
    auto load_rows = [&](int2 ci, int buf) {
        const void* pA = (ci.x >= 0) ? (const void*)(g_xh + (size_t)ci.x * CIN)
                                     : (const void*)g_zrow;
        const void* pB = (ci.y >= 0) ? (const void*)(g_xh + (size_t)ci.y * CIN)
                                     : (const void*)g_zrow;
        ldg256(pA, gA[buf][0], gA[buf][1]);
        ldg256(pB, gB[buf][0], gB[buf][1]);
    };

    load_rows(load_idx(0), 0);
    load_rows(load_idx(1), 1);
    int2 inext = load_idx(2);

#pragma unroll
    for (int k = 0; k < K2; k++) {
        int cur = k & 1;
        ((uint4*)arowA)[0] = gA[cur][0];
        ((uint4*)arowA)[1] = gA[cur][1];
        ((uint4*)arowB)[0] = gB[cur][0];
        ((uint4*)arowB)[1] = gB[cur][1];
        __syncwarp();
        if (k + 2 < K2) load_rows(inext, cur);     // idx already resolved
        if (k + 3 < K2) inext = load_idx(k + 3);
        unsigned bw[8];
        unsigned wtap = wb0 + k * (CIN * WSTR * 2) + lro * (WSTR * 2) + lco;
        ldsm4t(bw,     wtap);
        ldsm4t(bw + 4, wtap + 32);
#pragma unroll
        for (int m = 0; m < 4; m++) {
            unsigned av[4];
            ldsm4(av, abase + (16 * m + lro) * A1B + lco);
            mma16816(acc[m][0], av, bw[0], bw[1]);
            mma16816(acc[m][1], av, bw[2], bw[3]);
            mma16816(acc[m][2], av, bw[4], bw[5]);
            mma16816(acc[m][3], av, bw[6], bw[7]);
        }
        __syncwarp();
    }

    // epilogue: relu -> fp16 h1
#pragma unroll
    for (int m = 0; m < 4; m++) {
        int vg0 = v0w + 16 * m + grp, vg1 = vg0 + 8;
#pragma unroll
        for (int nt = 0; nt < 4; nt++) {
            const float* a = acc[m][nt];
            if (vg0 < n) {
                __half2 h = __floats2half2_rn(fmaxf(a[0], 0.f), fmaxf(a[1], 0.f));
                *(__half2*)(g_h1h + (size_t)vg0 * COUT + 8 * nt + 2 * tig) = h;
            }
            if (vg1 < n) {
                __half2 h = __floats2half2_rn(fmaxf(a[2], 0.f), fmaxf(a[3], 0.f));
                *(__half2*)(g_h1h + (size_t)vg1 * COUT + 8 * nt + 2 * tig) = h;
            }
        }
    }
}

// =====================================================================
// conv2 + residual (mask inline): warp tile M=64, 9 taps K=32.
// Pair-cooperative gathers (2 lanes / 64B row); idx prefetched 1 tap ahead.
// =====================================================================
__global__ __launch_bounds__(256, 2)
void conv2_kernel(const int* __restrict__ nbr_idx,
                  const unsigned* __restrict__ nbr_mask,
                  const float* __restrict__ b2, const float* __restrict__ bp,
                  float* __restrict__ out, int n) {
    extern __shared__ char smem[];
    __half* atile = (__half*)smem;                          // 8 * 64 * 80 B
    __half* wsm   = (__half*)(smem + 8 * 64 * AROW);        // 9*32*WSTR
    __half* wpsm  = wsm + K2 * COUT * WSTR;                 // 16*WSTR
    float*  bsm   = (float*)(wpsm + CIN * WSTR);

    const int t = threadIdx.x, lane = t & 31, w = t >> 5;
    for (int i = t; i < K2 * COUT * COUT; i += 256) {
        int row = i >> 5, cc = i & 31;
        wsm[row * WSTR + cc] = g_w2h[i];
    }
    for (int i = t; i < CIN * COUT; i += 256) {
        int row = i >> 5, cc = i & 31;
        wpsm[row * WSTR + cc] = g_wph[i];
    }
    if (t < COUT) bsm[t] = __ldg(b2 + t) + __ldg(bp + t);
    __syncthreads();

    const int grp = lane >> 2, tig = lane & 3;
    const int sub = lane & 7, ti = lane >> 3;
    const int v0w = blockIdx.x * 512 + w * 64;
    const int vA = v0w + lane, vB = vA + 32;

    const int prow = lane >> 1;      // pair-cooperative: row within 16-row segment
    const int phalf = lane & 1;      // which 32B half of the 64B row

    char* atw = (char*)atile + w * 64 * AROW;
    char* arowA = atw + lane * AROW;
    char* arowB = arowA + 32 * AROW;
    const unsigned abase = (unsigned)__cvta_generic_to_shared(atw);
    const unsigned wb0 = (unsigned)__cvta_generic_to_shared(wsm);
    const unsigned wpb = (unsigned)__cvta_generic_to_shared(wpsm);
    const int lro = sub + ((ti & 1) << 3);
    const int lco = (ti >> 1) << 4;

    float acc[4][4][4];
#pragma unroll
    for (int m = 0; m < 4; m++)
#pragma unroll
        for (int nt = 0; nt < 4; nt++) {
            float c0 = bsm[8 * nt + 2 * tig], c1 = bsm[8 * nt + 2 * tig + 1];
            acc[m][nt][0] = c0; acc[m][nt][1] = c1;
            acc[m][nt][2] = c0; acc[m][nt][3] = c1;
        }

    uint4 s[4][2];
    int4 inext;

    auto load_idx = [&](int k) -> int4 {
        int4 r;
#pragma unroll
        for (int seg = 0; seg < 4; seg++) {
            int vx = v0w + seg * 16 + prow;
            int ci = -1;
            if (vx < n) {
                int ix = __ldg(nbr_idx + (size_t)k * n + vx);
                unsigned mk = __ldg(nbr_mask + (size_t)k * n + vx);
                ci = sel_idx(ix, mk);
            }
            ((int*)&r)[seg] = ci;
        }
        return r;
    };
    auto load_rows = [&](int4 ci) {
#pragma unroll
        for (int seg = 0; seg < 4; seg++) {
            int c = ((const int*)&ci)[seg];
            const char* p = (c >= 0) ? (const char*)(g_h1h + (size_t)c * COUT)
                                     : (const char*)g_zrow;
            ldg256(p + phalf * 32, s[seg][0], s[seg][1]);
        }
    };
    auto sts_rows = [&]() {
#pragma unroll
        for (int seg = 0; seg < 4; seg++) {
            char* d = atw + (seg * 16 + prow) * AROW + phalf * 32;
            ((uint4*)d)[0] = s[seg][0];
            ((uint4*)d)[1] = s[seg][1];
        }
    };

    // ---- projection tap (K=16) from own fp16 x rows (coalesced) ----
    {
        uint4 p0, p1;
        if (vA < n) ldg256(g_xh + (size_t)vA * CIN, p0, p1);
        else { p0 = make_uint4(0, 0, 0, 0); p1 = p0; }
        ((uint4*)arowA)[0] = p0; ((uint4*)arowA)[1] = p1;
        if (vB < n) ldg256(g_xh + (size_t)vB * CIN, p0, p1);
        else { p0 = make_uint4(0, 0, 0, 0); p1 = p0; }
        ((uint4*)arowB)[0] = p0; ((uint4*)arowB)[1] = p1;
        __syncwarp();
    }

    // start gather pipeline (overlaps proj MMA)
    load_rows(load_idx(0));
    inext = load_idx(1);

    // proj MMA (K=16)
    {
        unsigned bw[8];
        unsigned wp0 = wpb + lro * (WSTR * 2) + lco;
        ldsm4t(bw,     wp0);
        ldsm4t(bw + 4, wp0 + 32);
#pragma unroll
        for (int m = 0; m < 4; m++) {
            unsigned av[4];
            ldsm4(av, abase + (16 * m + lro) * AROW + lco);
            mma16816(acc[m][0], av, bw[0], bw[1]);
            mma16816(acc[m][1], av, bw[2], bw[3]);
            mma16816(acc[m][2], av, bw[4], bw[5]);
            mma16816(acc[m][3], av, bw[6], bw[7]);
        }
        __syncwarp();
    }

    // ---- 9 conv taps (K=32) ----
#pragma unroll
    for (int k = 0; k < K2; k++) {
        sts_rows();
        __syncwarp();
        if (k + 1 < K2) load_rows(inext);      // idx already resolved
        if (k + 2 < K2) inext = load_idx(k + 2);
        unsigned wtap = wb0 + k * (COUT * WSTR * 2);
#pragma unroll
        for (int kt = 0; kt < 2; kt++) {
            unsigned bw[8];
            unsigned wk = wtap + (16 * kt + lro) * (WSTR * 2) + lco;
            ldsm4t(bw,     wk);
            ldsm4t(bw + 4, wk + 32);
#pragma unroll
            for (int m = 0; m < 4; m++) {
                unsigned av[4];
                ldsm4(av, abase + (16 * m + lro) * AROW + kt * 32 + lco);
                mma16816(acc[m][0], av, bw[0], bw[1]);
                mma16816(acc[m][1], av, bw[2], bw[3]);
                mma16816(acc[m][2], av, bw[4], bw[5]);
                mma16816(acc[m][3], av, bw[6], bw[7]);
            }
        }
        __syncwarp();
    }

    // epilogue: relu -> fp32 out
#pragma unroll
    for (int m = 0; m < 4; m++) {
        int vg0 = v0w + 16 * m + grp, vg1 = vg0 + 8;
#pragma unroll
        for (int nt = 0; nt < 4; nt++) {
            const float* a = acc[m][nt];
            if (vg0 < n)
                *(float2*)(out + (size_t)vg0 * COUT + 8 * nt + 2 * tig) =
                    make_float2(fmaxf(a[0], 0.f), fmaxf(a[1], 0.f));
            if (vg1 < n)
                *(float2*)(out + (size_t)vg1 * COUT + 8 * nt + 2 * tig) =
                    make_float2(fmaxf(a[2], 0.f), fmaxf(a[3], 0.f));
        }
    }
}

// =====================================================================
// Launch.  Input order: x, W1, b1, W2, b2, Wp, bp, nbr_idx, nbr_mask
// =====================================================================
extern "C" void kernel_launch(void* const* d_in, const int* in_sizes, int n_in,
                              void* d_out, int out_size) {
    const float* x  = (const float*)d_in[0];
    const float* W1 = (const float*)d_in[1];
    const float* b1 = (const float*)d_in[2];
    const float* W2 = (const float*)d_in[3];
    const float* b2 = (const float*)d_in[4];
    const float* Wp = (const float*)d_in[5];
    const float* bp = (const float*)d_in[6];
    const int* nbr_idx = (const int*)d_in[7];
    const unsigned* nbr_mask = (const unsigned*)d_in[8];
    float* out = (float*)d_out;

    int n = in_sizes[0] / CIN;
    if (n > MAXN) n = MAXN;

    const int smem2 = 8 * 64 * AROW + K2 * COUT * WSTR * 2 + CIN * WSTR * 2 + COUT * 4;
    cudaFuncSetAttribute(conv2_kernel, cudaFuncAttributeMaxDynamicSharedMemorySize, smem2);

    xhw_kernel<<<512, 256>>>(x, W1, W2, Wp, n);

    int blocks = (n + 511) / 512;
    conv1_kernel<<<blocks, 256>>>(nbr_idx, nbr_mask, b1, n);
    conv2_kernel<<<blocks, 256, smem2>>>(nbr_idx, nbr_mask, b2, bp, out, n);
}